// round 9
// baseline (speedup 1.0000x reference)
#include <cuda_runtime.h>
#include <cstdint>

#define NN 100000
#define EE 1600000
#define KF 128
#define SCAN_BLK 98           // ceil(100000/1024)

// ---------------- scratch (static device globals; no runtime alloc) ----------
__device__ __align__(16) float g_p[(size_t)NN * 128];   // X @ Wl^T
__device__ __align__(16) float g_r[(size_t)NN * 128];   // X @ Wr^T + b
__device__ __align__(16) float g_h[(size_t)NN * 128];   // layer-1 output
__device__ __align__(16) float g_h2[(size_t)NN * 64];   // dis-scaled layer-2 output
__device__ int   g_deg[NN];        // zeroed at END of each replay (and statically)
__device__ int   g_fill[NN];       // CSR write cursor (seeded = g_off in scanC)
__device__ int   g_off[NN + 1];
__device__ int   g_bsum[SCAN_BLK];
__device__ int   g_csrc[EE];
__device__ float g_rcnt[NN];
__device__ float g_dis[NN];

// ---------------- CSR build ------------------------------------------------------
__global__ void count_deg_kernel(const int4* __restrict__ dst4) {
    int e = blockIdx.x * blockDim.x + threadIdx.x;
    if (e < EE / 4) {
        int4 d = dst4[e];
        if ((unsigned)d.x < NN) atomicAdd(&g_deg[d.x], 1);
        if ((unsigned)d.y < NN) atomicAdd(&g_deg[d.y], 1);
        if ((unsigned)d.z < NN) atomicAdd(&g_deg[d.z], 1);
        if ((unsigned)d.w < NN) atomicAdd(&g_deg[d.w], 1);
    }
}

__global__ void scanA_kernel() {
    __shared__ int warp_sums[32];
    const int tid = threadIdx.x, lane = tid & 31, wid = tid >> 5;
    int i = blockIdx.x * 1024 + tid;
    int v = (i < NN) ? g_deg[i] : 0;
    int inc = v;
    #pragma unroll
    for (int o = 1; o < 32; o <<= 1) {
        int t = __shfl_up_sync(0xffffffffu, inc, o);
        if (lane >= o) inc += t;
    }
    if (lane == 31) warp_sums[wid] = inc;
    __syncthreads();
    if (wid == 0) {
        int s = warp_sums[lane];
        #pragma unroll
        for (int o = 1; o < 32; o <<= 1) {
            int t = __shfl_up_sync(0xffffffffu, s, o);
            if (lane >= o) s += t;
        }
        warp_sums[lane] = s;
    }
    __syncthreads();
    int warp_off = (wid > 0) ? warp_sums[wid - 1] : 0;
    if (i < NN) g_off[i] = warp_off + (inc - v);
    if (tid == 1023) g_bsum[blockIdx.x] = warp_sums[31];
}

// self-offsetting pass: add chunk offset, seed cursor, compute rcnt/dis.
__global__ void scanC_kernel() {
    __shared__ int s_off, s_tot;
    const int tid = threadIdx.x;
    const int chunk = blockIdx.x >> 2;
    if (tid < 32) {
        int p = 0, tot = 0;
        for (int j = tid; j < SCAN_BLK; j += 32) {
            int b = g_bsum[j];
            tot += b;
            if (j < chunk) p += b;
        }
        #pragma unroll
        for (int o = 16; o > 0; o >>= 1) {
            p   += __shfl_down_sync(0xffffffffu, p, o);
            tot += __shfl_down_sync(0xffffffffu, tot, o);
        }
        if (tid == 0) { s_off = p; s_tot = tot; }
    }
    __syncthreads();
    int i = blockIdx.x * 256 + tid;
    if (i < NN) {
        int off = g_off[i] + s_off;
        g_off[i]  = off;
        g_fill[i] = off;
        float d = (float)g_deg[i];
        g_rcnt[i] = 1.0f / fmaxf(d, 1.0f);
        g_dis[i]  = rsqrtf(d + 1.0f);
    }
    if (blockIdx.x == gridDim.x - 1 && tid == 0) g_off[NN] = s_tot;
}

__global__ void build_csr_kernel(const int4* __restrict__ src4,
                                 const int4* __restrict__ dst4) {
    int e = blockIdx.x * blockDim.x + threadIdx.x;
    if (e >= EE / 4) return;
    int4 d = dst4[e];
    int4 s = src4[e];
    if ((unsigned)d.x < NN && (unsigned)s.x < NN) g_csrc[atomicAdd(&g_fill[d.x], 1)] = s.x;
    if ((unsigned)d.y < NN && (unsigned)s.y < NN) g_csrc[atomicAdd(&g_fill[d.y], 1)] = s.y;
    if ((unsigned)d.z < NN && (unsigned)s.z < NN) g_csrc[atomicAdd(&g_fill[d.z], 1)] = s.z;
    if ((unsigned)d.w < NN && (unsigned)s.w < NN) g_csrc[atomicAdd(&g_fill[d.w], 1)] = s.w;
}

__global__ void zero_deg_kernel() {
    int v = blockIdx.x * blockDim.x + threadIdx.x;
    if (v < NN) g_deg[v] = 0;
}

// ---------------- tf32 helpers ---------------------------------------------------
__device__ __forceinline__ float2 tf32split2(float a) {
    uint32_t u;
    asm("cvt.rna.tf32.f32 %0, %1;" : "=r"(u) : "f"(a));
    float hi = __uint_as_float(u);
    float r = a - hi;
    asm("cvt.rna.tf32.f32 %0, %1;" : "=r"(u) : "f"(r));
    return make_float2(hi, __uint_as_float(u));
}

__device__ __forceinline__ void mma_tf32(float* c, const uint32_t* a, const uint32_t* b) {
    asm volatile(
        "mma.sync.aligned.m16n8k8.row.col.f32.tf32.tf32.f32 "
        "{%0,%1,%2,%3}, {%4,%5,%6,%7}, {%8,%9}, {%0,%1,%2,%3};"
        : "+f"(c[0]), "+f"(c[1]), "+f"(c[2]), "+f"(c[3])
        : "r"(a[0]), "r"(a[1]), "r"(a[2]), "r"(a[3]), "r"(b[0]), "r"(b[1]));
}

// ---------------- tensor-core dual GEMM: [P | R] = X @ [Wl | Wr]^T (+b on R) ----
// (hi,lo) packed as float2 in smem: fragment loads are LDS.64 (3x fewer LDS instrs)
template <int LAYER, int BNH>
__global__ void __launch_bounds__(256)
gemm_dual_tc(const float* __restrict__ xin,
             const float* __restrict__ Wl, const float* __restrict__ Wr,
             const float* __restrict__ bias) {
    constexpr int K = KF, BM = 128, BN = 64, BK = 16, LD = BK + 4;  // LD in float2 units
    __shared__ float2 sA[BM][LD];
    __shared__ float2 sB[BN][LD];

    const float* X = (LAYER == 1) ? xin : (const float*)g_h;
    const int tid = threadIdx.x;
    const int lane = tid & 31, wid = tid >> 5;
    const int wm = wid & 3, wn = wid >> 2;
    const int g = lane >> 2, t = lane & 3;
    const int row0 = blockIdx.x * BM;
    const int col0 = blockIdx.y * BN;

    float acc[2][4][4];
    #pragma unroll
    for (int mf = 0; mf < 2; mf++)
        #pragma unroll
        for (int nf = 0; nf < 4; nf++)
            #pragma unroll
            for (int i = 0; i < 4; i++) acc[mf][nf][i] = 0.f;

    for (int k0 = 0; k0 < K; k0 += BK) {
        #pragma unroll
        for (int i = 0; i < 2; i++) {
            int li = tid + i * 256;
            int r = li >> 2;
            int q = (li & 3) * 4;
            int gr = row0 + r;
            float4 v = (gr < NN) ? *(const float4*)&X[(size_t)gr * K + k0 + q]
                                 : make_float4(0.f, 0.f, 0.f, 0.f);
            sA[r][q]     = tf32split2(v.x);
            sA[r][q + 1] = tf32split2(v.y);
            sA[r][q + 2] = tf32split2(v.z);
            sA[r][q + 3] = tf32split2(v.w);
        }
        {
            int r = tid >> 2;
            int q = (tid & 3) * 4;
            int c = col0 + r;
            const float* Wsrc = (c < BNH) ? &Wl[(size_t)c * K] : &Wr[(size_t)(c - BNH) * K];
            float4 v = *(const float4*)&Wsrc[k0 + q];
            sB[r][q]     = tf32split2(v.x);
            sB[r][q + 1] = tf32split2(v.y);
            sB[r][q + 2] = tf32split2(v.z);
            sB[r][q + 3] = tf32split2(v.w);
        }
        __syncthreads();

        #pragma unroll
        for (int kk = 0; kk < BK; kk += 8) {
            uint32_t ah[2][4], al[2][4], bh[4][2], bl[4][2];
            #pragma unroll
            for (int mf = 0; mf < 2; mf++) {
                int rb = wm * 32 + mf * 16;
                float2 a0 = sA[rb + g][kk + t];
                float2 a1 = sA[rb + g + 8][kk + t];
                float2 a2 = sA[rb + g][kk + t + 4];
                float2 a3 = sA[rb + g + 8][kk + t + 4];
                ah[mf][0] = __float_as_uint(a0.x); al[mf][0] = __float_as_uint(a0.y);
                ah[mf][1] = __float_as_uint(a1.x); al[mf][1] = __float_as_uint(a1.y);
                ah[mf][2] = __float_as_uint(a2.x); al[mf][2] = __float_as_uint(a2.y);
                ah[mf][3] = __float_as_uint(a3.x); al[mf][3] = __float_as_uint(a3.y);
            }
            #pragma unroll
            for (int nf = 0; nf < 4; nf++) {
                int nb = wn * 32 + nf * 8;
                float2 b0 = sB[nb + g][kk + t];
                float2 b1 = sB[nb + g][kk + t + 4];
                bh[nf][0] = __float_as_uint(b0.x); bl[nf][0] = __float_as_uint(b0.y);
                bh[nf][1] = __float_as_uint(b1.x); bl[nf][1] = __float_as_uint(b1.y);
            }
            #pragma unroll
            for (int mf = 0; mf < 2; mf++)
                #pragma unroll
                for (int nf = 0; nf < 4; nf++) {
                    mma_tf32(acc[mf][nf], ah[mf], bh[nf]);   // hi*hi
                    mma_tf32(acc[mf][nf], ah[mf], bl[nf]);   // hi*lo
                    mma_tf32(acc[mf][nf], al[mf], bh[nf]);   // lo*hi
                }
        }
        __syncthreads();
    }

    const bool isP = (col0 < BNH);
    float* dstb = isP ? (float*)g_p : (float*)g_r;
    const int cb = col0 - (isP ? 0 : BNH);
    #pragma unroll
    for (int nf = 0; nf < 4; nf++) {
        int c = cb + wn * 32 + nf * 8 + 2 * t;
        float b0v = isP ? 0.f : bias[c];
        float b1v = isP ? 0.f : bias[c + 1];
        #pragma unroll
        for (int mf = 0; mf < 2; mf++) {
            int r = row0 + wm * 32 + mf * 16 + g;
            if (r < NN) {
                float2 o = make_float2(acc[mf][nf][0] + b0v, acc[mf][nf][1] + b1v);
                *(float2*)&dstb[(size_t)r * BNH + c] = o;
            }
            if (r + 8 < NN) {
                float2 o = make_float2(acc[mf][nf][2] + b0v, acc[mf][nf][3] + b1v);
                *(float2*)&dstb[(size_t)(r + 8) * BNH + c] = o;
            }
        }
    }
}

// ---------------- fused aggregation epilogues -----------------------------------
__global__ void agg128_relu_kernel() {
    int v = blockIdx.x * (blockDim.x >> 5) + (threadIdx.x >> 5);
    if (v >= NN) return;
    int lane = threadIdx.x & 31;
    const float* P = (const float*)g_p;
    int beg = g_off[v], end = g_off[v + 1];
    float4 acc = make_float4(0.f, 0.f, 0.f, 0.f);
    int j = beg;
    for (; j + 7 < end; j += 8) {
        float4 t0 = ((const float4*)(P + (size_t)g_csrc[j]     * 128))[lane];
        float4 t1 = ((const float4*)(P + (size_t)g_csrc[j + 1] * 128))[lane];
        float4 t2 = ((const float4*)(P + (size_t)g_csrc[j + 2] * 128))[lane];
        float4 t3 = ((const float4*)(P + (size_t)g_csrc[j + 3] * 128))[lane];
        float4 t4 = ((const float4*)(P + (size_t)g_csrc[j + 4] * 128))[lane];
        float4 t5 = ((const float4*)(P + (size_t)g_csrc[j + 5] * 128))[lane];
        float4 t6 = ((const float4*)(P + (size_t)g_csrc[j + 6] * 128))[lane];
        float4 t7 = ((const float4*)(P + (size_t)g_csrc[j + 7] * 128))[lane];
        acc.x += ((t0.x + t1.x) + (t2.x + t3.x)) + ((t4.x + t5.x) + (t6.x + t7.x));
        acc.y += ((t0.y + t1.y) + (t2.y + t3.y)) + ((t4.y + t5.y) + (t6.y + t7.y));
        acc.z += ((t0.z + t1.z) + (t2.z + t3.z)) + ((t4.z + t5.z) + (t6.z + t7.z));
        acc.w += ((t0.w + t1.w) + (t2.w + t3.w)) + ((t4.w + t5.w) + (t6.w + t7.w));
    }
    for (; j < end; j++) {
        float4 t = ((const float4*)(P + (size_t)g_csrc[j] * 128))[lane];
        acc.x += t.x; acc.y += t.y; acc.z += t.z; acc.w += t.w;
    }
    float rc = g_rcnt[v];
    float4 rr = ((const float4*)(g_r + (size_t)v * 128))[lane];
    float4 o;
    o.x = fmaxf(fmaf(acc.x, rc, rr.x), 0.f);
    o.y = fmaxf(fmaf(acc.y, rc, rr.y), 0.f);
    o.z = fmaxf(fmaf(acc.z, rc, rr.z), 0.f);
    o.w = fmaxf(fmaf(acc.w, rc, rr.w), 0.f);
    ((float4*)(g_h + (size_t)v * 128))[lane] = o;
}

// h2s[v] = dis[v] * (rcnt[v]*AggSum(P2) + R2[v])
__global__ void agg64_kernel() {
    int v = blockIdx.x * (blockDim.x >> 5) + (threadIdx.x >> 5);
    if (v >= NN) return;
    int lane = threadIdx.x & 31;
    const float* P = (const float*)g_p;   // stride 64
    int beg = g_off[v], end = g_off[v + 1];
    float ax = 0.f, ay = 0.f;
    int j = beg;
    for (; j + 7 < end; j += 8) {
        float2 t0 = ((const float2*)(P + (size_t)g_csrc[j]     * 64))[lane];
        float2 t1 = ((const float2*)(P + (size_t)g_csrc[j + 1] * 64))[lane];
        float2 t2 = ((const float2*)(P + (size_t)g_csrc[j + 2] * 64))[lane];
        float2 t3 = ((const float2*)(P + (size_t)g_csrc[j + 3] * 64))[lane];
        float2 t4 = ((const float2*)(P + (size_t)g_csrc[j + 4] * 64))[lane];
        float2 t5 = ((const float2*)(P + (size_t)g_csrc[j + 5] * 64))[lane];
        float2 t6 = ((const float2*)(P + (size_t)g_csrc[j + 6] * 64))[lane];
        float2 t7 = ((const float2*)(P + (size_t)g_csrc[j + 7] * 64))[lane];
        ax += ((t0.x + t1.x) + (t2.x + t3.x)) + ((t4.x + t5.x) + (t6.x + t7.x));
        ay += ((t0.y + t1.y) + (t2.y + t3.y)) + ((t4.y + t5.y) + (t6.y + t7.y));
    }
    for (; j < end; j++) {
        float2 t = ((const float2*)(P + (size_t)g_csrc[j] * 64))[lane];
        ax += t.x; ay += t.y;
    }
    float rc = g_rcnt[v];
    float dv = g_dis[v];
    float2 rr = ((const float2*)(g_r + (size_t)v * 64))[lane];
    float2 o;
    o.x = dv * fmaf(ax, rc, rr.x);
    o.y = dv * fmaf(ay, rc, rr.y);
    ((float2*)(g_h2 + (size_t)v * 64))[lane] = o;
}

// out[v] = dis[v] * (sum_e h2s[src] + h2s[v])
__global__ void iconv_kernel(float* __restrict__ out) {
    int v = blockIdx.x * (blockDim.x >> 5) + (threadIdx.x >> 5);
    if (v >= NN) return;
    const float* h2 = (const float*)g_h2;
    int lane = threadIdx.x & 31;
    float2 hv = ((const float2*)(h2 + (size_t)v * 64))[lane];
    float accx = hv.x, accy = hv.y;
    int beg = g_off[v], end = g_off[v + 1];
    int j = beg;
    for (; j + 7 < end; j += 8) {
        float2 t0 = ((const float2*)(h2 + (size_t)g_csrc[j]     * 64))[lane];
        float2 t1 = ((const float2*)(h2 + (size_t)g_csrc[j + 1] * 64))[lane];
        float2 t2 = ((const float2*)(h2 + (size_t)g_csrc[j + 2] * 64))[lane];
        float2 t3 = ((const float2*)(h2 + (size_t)g_csrc[j + 3] * 64))[lane];
        float2 t4 = ((const float2*)(h2 + (size_t)g_csrc[j + 4] * 64))[lane];
        float2 t5 = ((const float2*)(h2 + (size_t)g_csrc[j + 5] * 64))[lane];
        float2 t6 = ((const float2*)(h2 + (size_t)g_csrc[j + 6] * 64))[lane];
        float2 t7 = ((const float2*)(h2 + (size_t)g_csrc[j + 7] * 64))[lane];
        accx += ((t0.x + t1.x) + (t2.x + t3.x)) + ((t4.x + t5.x) + (t6.x + t7.x));
        accy += ((t0.y + t1.y) + (t2.y + t3.y)) + ((t4.y + t5.y) + (t6.y + t7.y));
    }
    for (; j < end; j++) {
        float2 t = ((const float2*)(h2 + (size_t)g_csrc[j] * 64))[lane];
        accx += t.x; accy += t.y;
    }
    float dv = g_dis[v];
    float2 r;
    r.x = dv * accx;
    r.y = dv * accy;
    ((float2*)(out + (size_t)v * 64))[lane] = r;
}

// ---------------- launcher ------------------------------------------------------
extern "C" void kernel_launch(void* const* d_in, const int* in_sizes, int n_in,
                              void* d_out, int out_size) {
    const float* x   = (const float*)d_in[0];
    const int*   ei  = (const int*)d_in[1];   // int32 (JAX x64 disabled)
    const float* W1l = (const float*)d_in[2];
    const float* b1  = (const float*)d_in[3];
    const float* W1r = (const float*)d_in[4];
    const float* W2l = (const float*)d_in[5];
    const float* b2  = (const float*)d_in[6];
    const float* W2r = (const float*)d_in[7];
    float* out = (float*)d_out;

    const int* src = ei;
    const int* dst = ei + EE;

    static cudaStream_t s_side = nullptr;
    static cudaEvent_t ev_fork = nullptr, ev_join = nullptr, ev_csr = nullptr, ev_zero = nullptr;
    static bool tried = false;
    if (!tried) {
        tried = true;
        bool ok = cudaStreamCreateWithFlags(&s_side, cudaStreamNonBlocking) == cudaSuccess &&
                  cudaEventCreateWithFlags(&ev_fork, cudaEventDisableTiming) == cudaSuccess &&
                  cudaEventCreateWithFlags(&ev_join, cudaEventDisableTiming) == cudaSuccess &&
                  cudaEventCreateWithFlags(&ev_csr,  cudaEventDisableTiming) == cudaSuccess &&
                  cudaEventCreateWithFlags(&ev_zero, cudaEventDisableTiming) == cudaSuccess;
        if (!ok) s_side = nullptr;
    }

    const int NB = (NN + 255) / 256;
    const int E4B = (EE / 4 + 255) / 256;
    const int WARP_GRID = (NN + 7) / 8;
    const dim3 G1((NN + 127) / 128, 4);   // N2 = 256
    const dim3 G2((NN + 127) / 128, 2);   // N2 = 128

    if (s_side) {
        cudaEventRecord(ev_fork, 0);
        cudaStreamWaitEvent(s_side, ev_fork, 0);
        gemm_dual_tc<1, 128><<<G1, 256, 0, s_side>>>(x, W1l, W1r, b1);
        cudaEventRecord(ev_join, s_side);

        count_deg_kernel<<<E4B, 256>>>((const int4*)dst);
        scanA_kernel<<<SCAN_BLK, 1024>>>();
        scanC_kernel<<<NB, 256>>>();
        cudaEventRecord(ev_csr, 0);
        cudaStreamWaitEvent(s_side, ev_csr, 0);
        zero_deg_kernel<<<NB, 256, 0, s_side>>>();
        cudaEventRecord(ev_zero, s_side);

        build_csr_kernel<<<E4B, 256>>>((const int4*)src, (const int4*)dst);
        cudaStreamWaitEvent(0, ev_join, 0);

        agg128_relu_kernel<<<WARP_GRID, 256>>>();
        gemm_dual_tc<2, 64><<<G2, 256>>>(x, W2l, W2r, b2);
        agg64_kernel<<<WARP_GRID, 256>>>();
        iconv_kernel<<<WARP_GRID, 256>>>(out);

        cudaStreamWaitEvent(0, ev_zero, 0);
    } else {
        zero_deg_kernel<<<NB, 256>>>();
        count_deg_kernel<<<E4B, 256>>>((const int4*)dst);
        scanA_kernel<<<SCAN_BLK, 1024>>>();
        scanC_kernel<<<NB, 256>>>();
        build_csr_kernel<<<E4B, 256>>>((const int4*)src, (const int4*)dst);
        gemm_dual_tc<1, 128><<<G1, 256>>>(x, W1l, W1r, b1);
        agg128_relu_kernel<<<WARP_GRID, 256>>>();
        gemm_dual_tc<2, 64><<<G2, 256>>>(x, W2l, W2r, b2);
        agg64_kernel<<<WARP_GRID, 256>>>();
        iconv_kernel<<<WARP_GRID, 256>>>(out);
    }
}

// round 10
// speedup vs baseline: 1.0147x; 1.0147x over previous
#include <cuda_runtime.h>
#include <cstdint>

#define NN 100000
#define EE 1600000
#define KF 128
#define SCAN_BLK 98           // ceil(100000/1024)

// ---------------- scratch (static device globals; no runtime alloc) ----------
__device__ __align__(16) float g_p[(size_t)NN * 128];   // X @ Wl^T
__device__ __align__(16) float g_r[(size_t)NN * 128];   // X @ Wr^T + b
__device__ __align__(16) float g_h[(size_t)NN * 128];   // layer-1 output
__device__ __align__(16) float g_h2[(size_t)NN * 64];   // dis-scaled layer-2 output
__device__ int   g_deg[NN];        // zeroed at END of each replay (and statically)
__device__ int   g_fill[NN];       // CSR write cursor (seeded = g_off in scanC)
__device__ int   g_off[NN + 1];
__device__ int   g_bsum[SCAN_BLK];
__device__ int   g_csrc[EE];
__device__ float g_rcnt[NN];
__device__ float g_dis[NN];

// ---------------- CSR build ------------------------------------------------------
__global__ void count_deg_kernel(const int4* __restrict__ dst4) {
    int e = blockIdx.x * blockDim.x + threadIdx.x;
    if (e < EE / 4) {
        int4 d = dst4[e];
        if ((unsigned)d.x < NN) atomicAdd(&g_deg[d.x], 1);
        if ((unsigned)d.y < NN) atomicAdd(&g_deg[d.y], 1);
        if ((unsigned)d.z < NN) atomicAdd(&g_deg[d.z], 1);
        if ((unsigned)d.w < NN) atomicAdd(&g_deg[d.w], 1);
    }
}

__global__ void scanA_kernel() {
    __shared__ int warp_sums[32];
    const int tid = threadIdx.x, lane = tid & 31, wid = tid >> 5;
    int i = blockIdx.x * 1024 + tid;
    int v = (i < NN) ? g_deg[i] : 0;
    int inc = v;
    #pragma unroll
    for (int o = 1; o < 32; o <<= 1) {
        int t = __shfl_up_sync(0xffffffffu, inc, o);
        if (lane >= o) inc += t;
    }
    if (lane == 31) warp_sums[wid] = inc;
    __syncthreads();
    if (wid == 0) {
        int s = warp_sums[lane];
        #pragma unroll
        for (int o = 1; o < 32; o <<= 1) {
            int t = __shfl_up_sync(0xffffffffu, s, o);
            if (lane >= o) s += t;
        }
        warp_sums[lane] = s;
    }
    __syncthreads();
    int warp_off = (wid > 0) ? warp_sums[wid - 1] : 0;
    if (i < NN) g_off[i] = warp_off + (inc - v);
    if (tid == 1023) g_bsum[blockIdx.x] = warp_sums[31];
}

// self-offsetting pass: add chunk offset, seed cursor, compute rcnt/dis.
__global__ void scanC_kernel() {
    __shared__ int s_off, s_tot;
    const int tid = threadIdx.x;
    const int chunk = blockIdx.x >> 2;
    if (tid < 32) {
        int p = 0, tot = 0;
        for (int j = tid; j < SCAN_BLK; j += 32) {
            int b = g_bsum[j];
            tot += b;
            if (j < chunk) p += b;
        }
        #pragma unroll
        for (int o = 16; o > 0; o >>= 1) {
            p   += __shfl_down_sync(0xffffffffu, p, o);
            tot += __shfl_down_sync(0xffffffffu, tot, o);
        }
        if (tid == 0) { s_off = p; s_tot = tot; }
    }
    __syncthreads();
    int i = blockIdx.x * 256 + tid;
    if (i < NN) {
        int off = g_off[i] + s_off;
        g_off[i]  = off;
        g_fill[i] = off;
        float d = (float)g_deg[i];
        g_rcnt[i] = 1.0f / fmaxf(d, 1.0f);
        g_dis[i]  = rsqrtf(d + 1.0f);
    }
    if (blockIdx.x == gridDim.x - 1 && tid == 0) g_off[NN] = s_tot;
}

__global__ void build_csr_kernel(const int4* __restrict__ src4,
                                 const int4* __restrict__ dst4) {
    int e = blockIdx.x * blockDim.x + threadIdx.x;
    if (e >= EE / 4) return;
    int4 d = dst4[e];
    int4 s = src4[e];
    if ((unsigned)d.x < NN && (unsigned)s.x < NN) g_csrc[atomicAdd(&g_fill[d.x], 1)] = s.x;
    if ((unsigned)d.y < NN && (unsigned)s.y < NN) g_csrc[atomicAdd(&g_fill[d.y], 1)] = s.y;
    if ((unsigned)d.z < NN && (unsigned)s.z < NN) g_csrc[atomicAdd(&g_fill[d.z], 1)] = s.z;
    if ((unsigned)d.w < NN && (unsigned)s.w < NN) g_csrc[atomicAdd(&g_fill[d.w], 1)] = s.w;
}

__global__ void zero_deg_kernel() {
    int v = blockIdx.x * blockDim.x + threadIdx.x;
    if (v < NN) g_deg[v] = 0;
}

// ---------------- tf32 helpers ---------------------------------------------------
__device__ __forceinline__ float2 tf32split2(float a) {
    uint32_t u;
    asm("cvt.rna.tf32.f32 %0, %1;" : "=r"(u) : "f"(a));
    float hi = __uint_as_float(u);
    float r = a - hi;
    asm("cvt.rna.tf32.f32 %0, %1;" : "=r"(u) : "f"(r));
    return make_float2(hi, __uint_as_float(u));
}

__device__ __forceinline__ void mma_tf32(float* c, const uint32_t* a, const uint32_t* b) {
    asm volatile(
        "mma.sync.aligned.m16n8k8.row.col.f32.tf32.tf32.f32 "
        "{%0,%1,%2,%3}, {%4,%5,%6,%7}, {%8,%9}, {%0,%1,%2,%3};"
        : "+f"(c[0]), "+f"(c[1]), "+f"(c[2]), "+f"(c[3])
        : "r"(a[0]), "r"(a[1]), "r"(a[2]), "r"(a[3]), "r"(b[0]), "r"(b[1]));
}

// ---------------- tensor-core dual GEMM: [P | R] = X @ [Wl | Wr]^T (+b on R) ----
// (hi,lo) packed as float2 in smem; LDS.64 fragment loads, per-phase conflict-free.
template <int LAYER, int BNH>
__global__ void __launch_bounds__(256)
gemm_dual_tc(const float* __restrict__ xin,
             const float* __restrict__ Wl, const float* __restrict__ Wr,
             const float* __restrict__ bias) {
    constexpr int K = KF, BM = 128, BN = 64, BK = 16, LD = BK + 4;  // LD in float2 units
    __shared__ float2 sA[BM][LD];
    __shared__ float2 sB[BN][LD];

    const float* X = (LAYER == 1) ? xin : (const float*)g_h;
    const int tid = threadIdx.x;
    const int lane = tid & 31, wid = tid >> 5;
    const int wm = wid & 3, wn = wid >> 2;
    const int g = lane >> 2, t = lane & 3;
    const int row0 = blockIdx.x * BM;
    const int col0 = blockIdx.y * BN;

    float acc[2][4][4];
    #pragma unroll
    for (int mf = 0; mf < 2; mf++)
        #pragma unroll
        for (int nf = 0; nf < 4; nf++)
            #pragma unroll
            for (int i = 0; i < 4; i++) acc[mf][nf][i] = 0.f;

    for (int k0 = 0; k0 < K; k0 += BK) {
        #pragma unroll
        for (int i = 0; i < 2; i++) {
            int li = tid + i * 256;
            int r = li >> 2;
            int q = (li & 3) * 4;
            int gr = row0 + r;
            float4 v = (gr < NN) ? *(const float4*)&X[(size_t)gr * K + k0 + q]
                                 : make_float4(0.f, 0.f, 0.f, 0.f);
            sA[r][q]     = tf32split2(v.x);
            sA[r][q + 1] = tf32split2(v.y);
            sA[r][q + 2] = tf32split2(v.z);
            sA[r][q + 3] = tf32split2(v.w);
        }
        {
            int r = tid >> 2;
            int q = (tid & 3) * 4;
            int c = col0 + r;
            const float* Wsrc = (c < BNH) ? &Wl[(size_t)c * K] : &Wr[(size_t)(c - BNH) * K];
            float4 v = *(const float4*)&Wsrc[k0 + q];
            sB[r][q]     = tf32split2(v.x);
            sB[r][q + 1] = tf32split2(v.y);
            sB[r][q + 2] = tf32split2(v.z);
            sB[r][q + 3] = tf32split2(v.w);
        }
        __syncthreads();

        #pragma unroll
        for (int kk = 0; kk < BK; kk += 8) {
            uint32_t ah[2][4], al[2][4], bh[4][2], bl[4][2];
            #pragma unroll
            for (int mf = 0; mf < 2; mf++) {
                int rb = wm * 32 + mf * 16;
                float2 a0 = sA[rb + g][kk + t];
                float2 a1 = sA[rb + g + 8][kk + t];
                float2 a2 = sA[rb + g][kk + t + 4];
                float2 a3 = sA[rb + g + 8][kk + t + 4];
                ah[mf][0] = __float_as_uint(a0.x); al[mf][0] = __float_as_uint(a0.y);
                ah[mf][1] = __float_as_uint(a1.x); al[mf][1] = __float_as_uint(a1.y);
                ah[mf][2] = __float_as_uint(a2.x); al[mf][2] = __float_as_uint(a2.y);
                ah[mf][3] = __float_as_uint(a3.x); al[mf][3] = __float_as_uint(a3.y);
            }
            #pragma unroll
            for (int nf = 0; nf < 4; nf++) {
                int nb = wn * 32 + nf * 8;
                float2 b0 = sB[nb + g][kk + t];
                float2 b1 = sB[nb + g][kk + t + 4];
                bh[nf][0] = __float_as_uint(b0.x); bl[nf][0] = __float_as_uint(b0.y);
                bh[nf][1] = __float_as_uint(b1.x); bl[nf][1] = __float_as_uint(b1.y);
            }
            #pragma unroll
            for (int mf = 0; mf < 2; mf++)
                #pragma unroll
                for (int nf = 0; nf < 4; nf++) {
                    mma_tf32(acc[mf][nf], ah[mf], bh[nf]);   // hi*hi
                    mma_tf32(acc[mf][nf], ah[mf], bl[nf]);   // hi*lo
                    mma_tf32(acc[mf][nf], al[mf], bh[nf]);   // lo*hi
                }
        }
        __syncthreads();
    }

    const bool isP = (col0 < BNH);
    float* dstb = isP ? (float*)g_p : (float*)g_r;
    const int cb = col0 - (isP ? 0 : BNH);
    #pragma unroll
    for (int nf = 0; nf < 4; nf++) {
        int c = cb + wn * 32 + nf * 8 + 2 * t;
        float b0v = isP ? 0.f : bias[c];
        float b1v = isP ? 0.f : bias[c + 1];
        #pragma unroll
        for (int mf = 0; mf < 2; mf++) {
            int r = row0 + wm * 32 + mf * 16 + g;
            if (r < NN) {
                float2 o = make_float2(acc[mf][nf][0] + b0v, acc[mf][nf][1] + b1v);
                *(float2*)&dstb[(size_t)r * BNH + c] = o;
            }
            if (r + 8 < NN) {
                float2 o = make_float2(acc[mf][nf][2] + b0v, acc[mf][nf][3] + b1v);
                *(float2*)&dstb[(size_t)(r + 8) * BNH + c] = o;
            }
        }
    }
}

// ---------------- fused aggregation epilogues (4-wide: MLP-safe) -----------------
__global__ void agg128_relu_kernel() {
    int v = blockIdx.x * (blockDim.x >> 5) + (threadIdx.x >> 5);
    if (v >= NN) return;
    int lane = threadIdx.x & 31;
    const float* P = (const float*)g_p;
    int beg = g_off[v], end = g_off[v + 1];
    float4 acc = make_float4(0.f, 0.f, 0.f, 0.f);
    int j = beg;
    for (; j + 3 < end; j += 4) {
        int s0 = g_csrc[j], s1 = g_csrc[j + 1], s2 = g_csrc[j + 2], s3 = g_csrc[j + 3];
        float4 t0 = ((const float4*)(P + (size_t)s0 * 128))[lane];
        float4 t1 = ((const float4*)(P + (size_t)s1 * 128))[lane];
        float4 t2 = ((const float4*)(P + (size_t)s2 * 128))[lane];
        float4 t3 = ((const float4*)(P + (size_t)s3 * 128))[lane];
        acc.x += (t0.x + t1.x) + (t2.x + t3.x);
        acc.y += (t0.y + t1.y) + (t2.y + t3.y);
        acc.z += (t0.z + t1.z) + (t2.z + t3.z);
        acc.w += (t0.w + t1.w) + (t2.w + t3.w);
    }
    for (; j < end; j++) {
        int s = g_csrc[j];
        float4 t = ((const float4*)(P + (size_t)s * 128))[lane];
        acc.x += t.x; acc.y += t.y; acc.z += t.z; acc.w += t.w;
    }
    float rc = g_rcnt[v];
    float4 rr = ((const float4*)(g_r + (size_t)v * 128))[lane];
    float4 o;
    o.x = fmaxf(fmaf(acc.x, rc, rr.x), 0.f);
    o.y = fmaxf(fmaf(acc.y, rc, rr.y), 0.f);
    o.z = fmaxf(fmaf(acc.z, rc, rr.z), 0.f);
    o.w = fmaxf(fmaf(acc.w, rc, rr.w), 0.f);
    ((float4*)(g_h + (size_t)v * 128))[lane] = o;
}

// h2s[v] = dis[v] * (rcnt[v]*AggSum(P2) + R2[v])
__global__ void agg64_kernel() {
    int v = blockIdx.x * (blockDim.x >> 5) + (threadIdx.x >> 5);
    if (v >= NN) return;
    int lane = threadIdx.x & 31;
    const float* P = (const float*)g_p;   // stride 64
    int beg = g_off[v], end = g_off[v + 1];
    float ax = 0.f, ay = 0.f;
    int j = beg;
    for (; j + 3 < end; j += 4) {
        int s0 = g_csrc[j], s1 = g_csrc[j + 1], s2 = g_csrc[j + 2], s3 = g_csrc[j + 3];
        float2 t0 = ((const float2*)(P + (size_t)s0 * 64))[lane];
        float2 t1 = ((const float2*)(P + (size_t)s1 * 64))[lane];
        float2 t2 = ((const float2*)(P + (size_t)s2 * 64))[lane];
        float2 t3 = ((const float2*)(P + (size_t)s3 * 64))[lane];
        ax += (t0.x + t1.x) + (t2.x + t3.x);
        ay += (t0.y + t1.y) + (t2.y + t3.y);
    }
    for (; j < end; j++) {
        int s = g_csrc[j];
        float2 t = ((const float2*)(P + (size_t)s * 64))[lane];
        ax += t.x; ay += t.y;
    }
    float rc = g_rcnt[v];
    float dv = g_dis[v];
    float2 rr = ((const float2*)(g_r + (size_t)v * 64))[lane];
    float2 o;
    o.x = dv * fmaf(ax, rc, rr.x);
    o.y = dv * fmaf(ay, rc, rr.y);
    ((float2*)(g_h2 + (size_t)v * 64))[lane] = o;
}

// out[v] = dis[v] * (sum_e h2s[src] + h2s[v])
__global__ void iconv_kernel(float* __restrict__ out) {
    int v = blockIdx.x * (blockDim.x >> 5) + (threadIdx.x >> 5);
    if (v >= NN) return;
    const float* h2 = (const float*)g_h2;
    int lane = threadIdx.x & 31;
    float2 hv = ((const float2*)(h2 + (size_t)v * 64))[lane];
    float accx = hv.x, accy = hv.y;
    int beg = g_off[v], end = g_off[v + 1];
    int j = beg;
    for (; j + 3 < end; j += 4) {
        int s0 = g_csrc[j], s1 = g_csrc[j + 1], s2 = g_csrc[j + 2], s3 = g_csrc[j + 3];
        float2 t0 = ((const float2*)(h2 + (size_t)s0 * 64))[lane];
        float2 t1 = ((const float2*)(h2 + (size_t)s1 * 64))[lane];
        float2 t2 = ((const float2*)(h2 + (size_t)s2 * 64))[lane];
        float2 t3 = ((const float2*)(h2 + (size_t)s3 * 64))[lane];
        accx += (t0.x + t1.x) + (t2.x + t3.x);
        accy += (t0.y + t1.y) + (t2.y + t3.y);
    }
    for (; j < end; j++) {
        int s = g_csrc[j];
        float2 t = ((const float2*)(h2 + (size_t)s * 64))[lane];
        accx += t.x; accy += t.y;
    }
    float dv = g_dis[v];
    float2 r;
    r.x = dv * accx;
    r.y = dv * accy;
    ((float2*)(out + (size_t)v * 64))[lane] = r;
}

// ---------------- launcher ------------------------------------------------------
extern "C" void kernel_launch(void* const* d_in, const int* in_sizes, int n_in,
                              void* d_out, int out_size) {
    const float* x   = (const float*)d_in[0];
    const int*   ei  = (const int*)d_in[1];   // int32 (JAX x64 disabled)
    const float* W1l = (const float*)d_in[2];
    const float* b1  = (const float*)d_in[3];
    const float* W1r = (const float*)d_in[4];
    const float* W2l = (const float*)d_in[5];
    const float* b2  = (const float*)d_in[6];
    const float* W2r = (const float*)d_in[7];
    float* out = (float*)d_out;

    const int* src = ei;
    const int* dst = ei + EE;

    static cudaStream_t s_side = nullptr;
    static cudaEvent_t ev_fork = nullptr, ev_join = nullptr, ev_csr = nullptr, ev_zero = nullptr;
    static bool tried = false;
    if (!tried) {
        tried = true;
        bool ok = cudaStreamCreateWithFlags(&s_side, cudaStreamNonBlocking) == cudaSuccess &&
                  cudaEventCreateWithFlags(&ev_fork, cudaEventDisableTiming) == cudaSuccess &&
                  cudaEventCreateWithFlags(&ev_join, cudaEventDisableTiming) == cudaSuccess &&
                  cudaEventCreateWithFlags(&ev_csr,  cudaEventDisableTiming) == cudaSuccess &&
                  cudaEventCreateWithFlags(&ev_zero, cudaEventDisableTiming) == cudaSuccess;
        if (!ok) s_side = nullptr;
    }

    const int NB = (NN + 255) / 256;
    const int E4B = (EE / 4 + 255) / 256;
    const int WARP_GRID = (NN + 7) / 8;
    const dim3 G1((NN + 127) / 128, 4);   // N2 = 256
    const dim3 G2((NN + 127) / 128, 2);   // N2 = 128

    if (s_side) {
        cudaEventRecord(ev_fork, 0);
        cudaStreamWaitEvent(s_side, ev_fork, 0);
        gemm_dual_tc<1, 128><<<G1, 256, 0, s_side>>>(x, W1l, W1r, b1);
        cudaEventRecord(ev_join, s_side);

        count_deg_kernel<<<E4B, 256>>>((const int4*)dst);
        scanA_kernel<<<SCAN_BLK, 1024>>>();
        scanC_kernel<<<NB, 256>>>();
        cudaEventRecord(ev_csr, 0);
        cudaStreamWaitEvent(s_side, ev_csr, 0);
        zero_deg_kernel<<<NB, 256, 0, s_side>>>();
        cudaEventRecord(ev_zero, s_side);

        build_csr_kernel<<<E4B, 256>>>((const int4*)src, (const int4*)dst);
        cudaStreamWaitEvent(0, ev_join, 0);

        agg128_relu_kernel<<<WARP_GRID, 256>>>();
        gemm_dual_tc<2, 64><<<G2, 256>>>(x, W2l, W2r, b2);
        agg64_kernel<<<WARP_GRID, 256>>>();
        iconv_kernel<<<WARP_GRID, 256>>>(out);

        cudaStreamWaitEvent(0, ev_zero, 0);
    } else {
        zero_deg_kernel<<<NB, 256>>>();
        count_deg_kernel<<<E4B, 256>>>((const int4*)dst);
        scanA_kernel<<<SCAN_BLK, 1024>>>();
        scanC_kernel<<<NB, 256>>>();
        build_csr_kernel<<<E4B, 256>>>((const int4*)src, (const int4*)dst);
        gemm_dual_tc<1, 128><<<G1, 256>>>(x, W1l, W1r, b1);
        agg128_relu_kernel<<<WARP_GRID, 256>>>();
        gemm_dual_tc<2, 64><<<G2, 256>>>(x, W2l, W2r, b2);
        agg64_kernel<<<WARP_GRID, 256>>>();
        iconv_kernel<<<WARP_GRID, 256>>>(out);
    }
}